// round 9
// baseline (speedup 1.0000x reference)
#include <cuda_runtime.h>
#include <cstdint>

#define NBH 64
#define L   512
#define DD  64
#define SQP 68    // sQ row pad (floats)
#define SKP 260   // sKT row pad (floats), 1040B = 65*16 -> float4 aligned
#define SPP 68    // sP row pad
#define SVP 68    // sV row pad

typedef unsigned long long ull;

// Scratch (device globals; no allocation in kernel_launch)
__device__ float  g_ksumT[NBH * DD * L];   // [bh][d][j]  (transposed)
__device__ float  g_vsum [NBH * L * DD];   // [bh][j][d]  (natural)
__device__ float2 g_stats[NBH * L];        // per attn row: {M, 1/Z}

__device__ __forceinline__ ull pack2(float x) {
    ull r; unsigned int xi = __float_as_uint(x);
    asm("mov.b64 %0, {%1, %1};" : "=l"(r) : "r"(xi));
    return r;
}
__device__ __forceinline__ void ffma2(ull& c, ull a, ull b) {
    asm("fma.rn.f32x2 %0, %1, %2, %0;" : "+l"(c) : "l"(a), "l"(b));
}
__device__ __forceinline__ float2 unpack2(ull x) {
    float2 f;
    asm("mov.b64 {%0, %1}, %2;" : "=f"(f.x), "=f"(f.y) : "l"(x));
    return f;
}

// ---------------------------------------------------------------------------
// K1: reduce r; write ksum TRANSPOSED [bh][d][j] (via smem tile transpose)
//     and vsum natural [bh][j][d]. grid (8 jblocks, 64 bh) x 256 threads.
// ---------------------------------------------------------------------------
__global__ __launch_bounds__(256)
void reduce_kv_kernel(const float* __restrict__ k, const float* __restrict__ v) {
    __shared__ float sT[DD * 65];
    const int t  = threadIdx.x;
    const int jb = blockIdx.x;
    const int bh = blockIdx.y;

    #pragma unroll
    for (int p = 0; p < 4; ++p) {
        int f4 = p * 256 + t;
        int jl = f4 >> 4, dq = (f4 & 15) << 2;
        size_t base = (((size_t)bh * L + jb * 64 + jl) * 4) * DD + dq;
        float4 a0 = *(const float4*)(k + base);
        float4 a1 = *(const float4*)(k + base + DD);
        float4 a2 = *(const float4*)(k + base + 2 * DD);
        float4 a3 = *(const float4*)(k + base + 3 * DD);
        float ks0 = (a0.x + a1.x) + (a2.x + a3.x);
        float ks1 = (a0.y + a1.y) + (a2.y + a3.y);
        float ks2 = (a0.z + a1.z) + (a2.z + a3.z);
        float ks3 = (a0.w + a1.w) + (a2.w + a3.w);
        sT[(dq + 0) * 65 + jl] = ks0;
        sT[(dq + 1) * 65 + jl] = ks1;
        sT[(dq + 2) * 65 + jl] = ks2;
        sT[(dq + 3) * 65 + jl] = ks3;
        float4 b0 = *(const float4*)(v + base);
        float4 b1 = *(const float4*)(v + base + DD);
        float4 b2 = *(const float4*)(v + base + 2 * DD);
        float4 b3 = *(const float4*)(v + base + 3 * DD);
        float4 vs;
        vs.x = (b0.x + b1.x) + (b2.x + b3.x);
        vs.y = (b0.y + b1.y) + (b2.y + b3.y);
        vs.z = (b0.z + b1.z) + (b2.z + b3.z);
        vs.w = (b0.w + b1.w) + (b2.w + b3.w);
        *(float4*)(g_vsum + ((size_t)bh * L + jb * 64 + jl) * DD + dq) = vs;
    }
    __syncthreads();
    #pragma unroll
    for (int p = 0; p < 4; ++p) {
        int f4 = p * 256 + t;
        int dl = f4 >> 4, jq = (f4 & 15) << 2;
        float4 o;
        o.x = sT[dl * 65 + jq + 0];
        o.y = sT[dl * 65 + jq + 1];
        o.z = sT[dl * 65 + jq + 2];
        o.w = sT[dl * 65 + jq + 3];
        *(float4*)(g_ksumT + ((size_t)bh * DD + dl) * L + jb * 64 + jq) = o;
    }
}

// ---------------------------------------------------------------------------
// K2: S = (Q/8)@KsumT, apply omega/mask, write RAW S to attn region,
//     online per-row max/sum -> g_stats. No S in smem: warp owns 8 rows,
//     lane owns cols {4l..4l+3, 128+4l..128+4l+3} per 256-col chunk.
// grid (8, 64) x 256. smem = sQ[64][68] + sKT[64][260] = 84KB -> 2 CTA/SM.
// ---------------------------------------------------------------------------
extern __shared__ float smem[];

__global__ __launch_bounds__(256, 2)
void score_kernel(const float* __restrict__ q,
                  const float* __restrict__ omega,
                  const int*   __restrict__ mask,
                  float* __restrict__ sraw) {
    float* sQ  = smem;              // [64][SQP]
    float* sKT = smem + 64 * SQP;   // [64][SKP]

    const int t  = threadIdx.x;
    const int bh = blockIdx.y;
    const int b  = bh >> 3;
    const int qb = blockIdx.x * 64;
    const int w  = t >> 5, l = t & 31;

    // fill sQ (natural layout, fold 1/8)
    #pragma unroll
    for (int p = 0; p < 4; ++p) {
        int f4 = p * 256 + t;
        int r = f4 >> 4, dq = (f4 & 15) << 2;
        float4 qv = *(const float4*)(q + ((size_t)bh * L + qb + r) * DD + dq);
        qv.x *= 0.125f; qv.y *= 0.125f; qv.z *= 0.125f; qv.w *= 0.125f;
        *(float4*)(sQ + r * SQP + dq) = qv;
    }

    float M[8], Z[8];
    #pragma unroll
    for (int r = 0; r < 8; ++r) { M[r] = -3.4e38f; Z[r] = 0.f; }

    for (int c = 0; c < 2; ++c) {
        __syncthreads();
        // fill sKT chunk (dense copy from pre-transposed g_ksumT)
        #pragma unroll
        for (int p = 0; p < 16; ++p) {
            int f4 = p * 256 + t;
            int d = f4 >> 6, cq = (f4 & 63) << 2;
            float4 kv = *(const float4*)(g_ksumT + ((size_t)bh * DD + d) * L + c * 256 + cq);
            *(float4*)(sKT + d * SKP + cq) = kv;
        }
        __syncthreads();

        ull acc[8][4];
        #pragma unroll
        for (int r = 0; r < 8; ++r)
            #pragma unroll
            for (int i = 0; i < 4; ++i) acc[r][i] = 0;

        const float* bp = sKT + 4 * l;
        #pragma unroll 2
        for (int d = 0; d < DD; d += 2) {
            float2 a[8];
            #pragma unroll
            for (int r = 0; r < 8; ++r)
                a[r] = *(const float2*)(sQ + (8 * w + r) * SQP + d);
            #pragma unroll
            for (int dd = 0; dd < 2; ++dd) {
                ulonglong2 b0 = *(const ulonglong2*)(bp + (d + dd) * SKP);
                ulonglong2 b1 = *(const ulonglong2*)(bp + (d + dd) * SKP + 128);
                #pragma unroll
                for (int r = 0; r < 8; ++r) {
                    ull ar = pack2(dd ? a[r].y : a[r].x);
                    ffma2(acc[r][0], ar, b0.x);
                    ffma2(acc[r][1], ar, b0.y);
                    ffma2(acc[r][2], ar, b1.x);
                    ffma2(acc[r][3], ar, b1.y);
                }
            }
        }

        // epilogue: omega, mask, raw store, online softmax stats
        #pragma unroll
        for (int r = 0; r < 8; ++r) {
            int gi = qb + 8 * w + r;
            size_t orow = ((size_t)b * L + gi) * L + c * 256;
            float4 o0 = *(const float4*)(omega + orow + 4 * l);
            float4 o1 = *(const float4*)(omega + orow + 128 + 4 * l);
            int4 m0 = *(const int4*)(mask + orow + 4 * l);
            int4 m1 = *(const int4*)(mask + orow + 128 + 4 * l);
            float2 u0 = unpack2(acc[r][0]), u1 = unpack2(acc[r][1]);
            float2 u2 = unpack2(acc[r][2]), u3 = unpack2(acc[r][3]);
            float s0 = m0.x ? -1e9f : u0.x * o0.x;
            float s1 = m0.y ? -1e9f : u0.y * o0.y;
            float s2 = m0.z ? -1e9f : u1.x * o0.z;
            float s3 = m0.w ? -1e9f : u1.y * o0.w;
            float s4 = m1.x ? -1e9f : u2.x * o1.x;
            float s5 = m1.y ? -1e9f : u2.y * o1.y;
            float s6 = m1.z ? -1e9f : u3.x * o1.z;
            float s7 = m1.w ? -1e9f : u3.y * o1.w;

            size_t arow = ((size_t)bh * L + gi) * L + c * 256;
            *(float4*)(sraw + arow + 4 * l)       = make_float4(s0, s1, s2, s3);
            *(float4*)(sraw + arow + 128 + 4 * l) = make_float4(s4, s5, s6, s7);

            float cm = fmaxf(fmaxf(fmaxf(s0, s1), fmaxf(s2, s3)),
                             fmaxf(fmaxf(s4, s5), fmaxf(s6, s7)));
            #pragma unroll
            for (int o = 16; o > 0; o >>= 1)
                cm = fmaxf(cm, __shfl_xor_sync(0xffffffffu, cm, o));
            float nM = fmaxf(M[r], cm);
            float cs = __expf(s0 - nM) + __expf(s1 - nM) + __expf(s2 - nM) + __expf(s3 - nM)
                     + __expf(s4 - nM) + __expf(s5 - nM) + __expf(s6 - nM) + __expf(s7 - nM);
            #pragma unroll
            for (int o = 16; o > 0; o >>= 1)
                cs += __shfl_xor_sync(0xffffffffu, cs, o);
            Z[r] = Z[r] * __expf(M[r] - nM) + cs;
            M[r] = nM;
        }
    }
    if (l == 0) {
        #pragma unroll
        for (int r = 0; r < 8; ++r) {
            int gi = qb + 8 * w + r;
            g_stats[(size_t)bh * L + gi] = make_float2(M[r], 1.0f / Z[r]);
        }
    }
}

// ---------------------------------------------------------------------------
// K3: P = exp(S-M)/Z (written in place to attn) and O = P @ Vsum.
// grid 256 (4 tiles of 128 rows per bh) x 256. warp=16 rows, lane=2 d-cols.
// smem = sP[128][68] + sV[64][68] + sSt[256] = 53KB -> 2 CTA/SM.
// ---------------------------------------------------------------------------
__global__ __launch_bounds__(256, 2)
void out_kernel(float* __restrict__ attn, float* __restrict__ out_o) {
    float* sP  = smem;                    // [128][SPP]
    float* sV  = smem + 128 * SPP;        // [64][SVP]
    float* sSt = sV + 64 * SVP;           // 128 x {M, invZ}

    const int t  = threadIdx.x;
    const int bx = blockIdx.x;
    const int bh = bx >> 2;
    const int ib = (bx & 3) * 128;
    const int w  = t >> 5, l = t & 31;

    if (t < 128) {
        float2 st = g_stats[(size_t)bh * L + ib + t];
        sSt[2 * t] = st.x; sSt[2 * t + 1] = st.y;
    }

    ull acc[16];
    #pragma unroll
    for (int rr = 0; rr < 16; ++rr) acc[rr] = 0;

    for (int jc = 0; jc < 8; ++jc) {
        __syncthreads();
        // fill sV (dense copy)
        #pragma unroll
        for (int p = 0; p < 4; ++p) {
            int f4 = p * 256 + t;
            int j = f4 >> 4, dq = (f4 & 15) << 2;
            *(float4*)(sV + j * SVP + dq) =
                *(const float4*)(g_vsum + ((size_t)bh * L + jc * 64 + j) * DD + dq);
        }
        // fill sP: read raw S, exp, write final P back to gmem + smem
        #pragma unroll
        for (int p = 0; p < 8; ++p) {
            int f4 = p * 256 + t;
            int row = f4 >> 4, jq = (f4 & 15) << 2;
            size_t ga = ((size_t)bh * L + ib + row) * L + jc * 64 + jq;
            float4 rv = *(const float4*)(attn + ga);
            float mM = sSt[2 * row], iz = sSt[2 * row + 1];
            float4 pv;
            pv.x = __expf(rv.x - mM) * iz;
            pv.y = __expf(rv.y - mM) * iz;
            pv.z = __expf(rv.z - mM) * iz;
            pv.w = __expf(rv.w - mM) * iz;
            *(float4*)(attn + ga) = pv;
            *(float4*)(sP + row * SPP + jq) = pv;
        }
        __syncthreads();

        #pragma unroll 2
        for (int j = 0; j < 64; j += 2) {
            float2 a[16];
            #pragma unroll
            for (int rr = 0; rr < 16; ++rr)
                a[rr] = *(const float2*)(sP + (w * 16 + rr) * SPP + j);
            #pragma unroll
            for (int jj = 0; jj < 2; ++jj) {
                ull bb = *(const ull*)(sV + (j + jj) * SVP + 2 * l);
                #pragma unroll
                for (int rr = 0; rr < 16; ++rr)
                    ffma2(acc[rr], pack2(jj ? a[rr].y : a[rr].x), bb);
            }
        }
    }

    #pragma unroll
    for (int rr = 0; rr < 16; ++rr) {
        float2 ov = unpack2(acc[rr]);
        *(float2*)(out_o + ((size_t)bh * L + ib + w * 16 + rr) * DD + 2 * l) = ov;
    }
}

// ---------------------------------------------------------------------------
extern "C" void kernel_launch(void* const* d_in, const int* in_sizes, int n_in,
                              void* d_out, int out_size) {
    const float* q     = (const float*)d_in[0];
    const float* k     = (const float*)d_in[1];
    const float* v     = (const float*)d_in[2];
    const float* omega = (const float*)d_in[3];
    const int*   mask  = (const int*)d_in[4];

    float* out_o    = (float*)d_out;
    float* out_attn = out_o + (size_t)NBH * L * DD;   // [output | attn]

    const int smem2 = (64 * SQP + 64 * SKP) * (int)sizeof(float);        // 83968
    const int smem3 = (128 * SPP + 64 * SVP + 256) * (int)sizeof(float); // 53248
    cudaFuncSetAttribute(score_kernel, cudaFuncAttributeMaxDynamicSharedMemorySize, smem2);
    cudaFuncSetAttribute(out_kernel,   cudaFuncAttributeMaxDynamicSharedMemorySize, smem3);

    reduce_kv_kernel<<<dim3(8, NBH), 256>>>(k, v);
    score_kernel<<<dim3(8, NBH), 256, smem2>>>(q, omega, mask, out_attn);
    out_kernel<<<256, 256, smem3>>>(out_attn, out_o);
}

// round 10
// speedup vs baseline: 1.0375x; 1.0375x over previous
#include <cuda_runtime.h>
#include <cstdint>

#define NBH 64
#define L   512
#define DD  64
#define SQP 68    // sQ / sV row pad (floats)
#define SKP 260   // sKT / sP row pad (floats)
#define SVP 68

typedef unsigned long long ull;

// Scratch (device globals; no allocation in kernel_launch)
__device__ float g_ksumT[NBH * DD * L];   // [bh][d][j]  (transposed)
__device__ float g_vsum [NBH * L * DD];   // [bh][j][d]  (natural)

__device__ __forceinline__ ull pack2(float x) {
    ull r; unsigned int xi = __float_as_uint(x);
    asm("mov.b64 %0, {%1, %1};" : "=l"(r) : "r"(xi));
    return r;
}
__device__ __forceinline__ void ffma2(ull& c, ull a, ull b) {
    asm("fma.rn.f32x2 %0, %1, %2, %0;" : "+l"(c) : "l"(a), "l"(b));
}
__device__ __forceinline__ float2 unpack2(ull x) {
    float2 f;
    asm("mov.b64 {%0, %1}, %2;" : "=f"(f.x), "=f"(f.y) : "l"(x));
    return f;
}

// ---------------------------------------------------------------------------
// K1: reduce r; ksum TRANSPOSED [bh][d][j] via smem transpose, vsum natural.
// ---------------------------------------------------------------------------
__global__ __launch_bounds__(256)
void reduce_kv_kernel(const float* __restrict__ k, const float* __restrict__ v) {
    __shared__ float sT[DD * 65];
    const int t  = threadIdx.x;
    const int jb = blockIdx.x;
    const int bh = blockIdx.y;

    #pragma unroll
    for (int p = 0; p < 4; ++p) {
        int f4 = p * 256 + t;
        int jl = f4 >> 4, dq = (f4 & 15) << 2;
        size_t base = (((size_t)bh * L + jb * 64 + jl) * 4) * DD + dq;
        float4 a0 = *(const float4*)(k + base);
        float4 a1 = *(const float4*)(k + base + DD);
        float4 a2 = *(const float4*)(k + base + 2 * DD);
        float4 a3 = *(const float4*)(k + base + 3 * DD);
        sT[(dq + 0) * 65 + jl] = (a0.x + a1.x) + (a2.x + a3.x);
        sT[(dq + 1) * 65 + jl] = (a0.y + a1.y) + (a2.y + a3.y);
        sT[(dq + 2) * 65 + jl] = (a0.z + a1.z) + (a2.z + a3.z);
        sT[(dq + 3) * 65 + jl] = (a0.w + a1.w) + (a2.w + a3.w);
        float4 b0 = *(const float4*)(v + base);
        float4 b1 = *(const float4*)(v + base + DD);
        float4 b2 = *(const float4*)(v + base + 2 * DD);
        float4 b3 = *(const float4*)(v + base + 3 * DD);
        float4 vs;
        vs.x = (b0.x + b1.x) + (b2.x + b3.x);
        vs.y = (b0.y + b1.y) + (b2.y + b3.y);
        vs.z = (b0.z + b1.z) + (b2.z + b3.z);
        vs.w = (b0.w + b1.w) + (b2.w + b3.w);
        *(float4*)(g_vsum + ((size_t)bh * L + jb * 64 + jl) * DD + dq) = vs;
    }
    __syncthreads();
    #pragma unroll
    for (int p = 0; p < 4; ++p) {
        int f4 = p * 256 + t;
        int dl = f4 >> 4, jq = (f4 & 15) << 2;
        float4 o;
        o.x = sT[dl * 65 + jq + 0];
        o.y = sT[dl * 65 + jq + 1];
        o.z = sT[dl * 65 + jq + 2];
        o.w = sT[dl * 65 + jq + 3];
        *(float4*)(g_ksumT + ((size_t)bh * DD + dl) * L + jb * 64 + jq) = o;
    }
}

// ---------------------------------------------------------------------------
// K2 (fused): per CTA 64 q rows of one bh.
//   c=0: S chunk -> raw store to attn, online stats
//   c=1: S chunk -> stats finalize -> normalized P to attn + sP(smem)
//   PV chunk1 from sP; chunk0 fixup (L2 re-read, normalize, attn + sP);
//   PV chunk0; write O.
// smem: sQ[64][68] (aliased by sV) | sKT[64][260] (aliased by sP) = 84KB.
// ---------------------------------------------------------------------------
extern __shared__ float smem[];

__global__ __launch_bounds__(256, 2)
void attn_fused(const float* __restrict__ q,
                const float* __restrict__ omega,
                const int*   __restrict__ mask,
                float* __restrict__ attn,
                float* __restrict__ out_o) {
    float* sQ  = smem;              // [64][SQP]
    float* sKT = smem + 64 * SQP;   // [64][SKP]
    float* sV  = sQ;                // alias (sQ dead after QK mainloops)
    float* sP  = sKT;               // alias (sKT dead after c=1 mainloop)

    const int t  = threadIdx.x;
    const int bh = blockIdx.y;
    const int b  = bh >> 3;
    const int qb = blockIdx.x * 64;
    const int w  = t >> 5, l = t & 31;

    // fill sQ (fold 1/8)
    #pragma unroll
    for (int p = 0; p < 4; ++p) {
        int f4 = p * 256 + t;
        int r = f4 >> 4, dq = (f4 & 15) << 2;
        float4 qv = *(const float4*)(q + ((size_t)bh * L + qb + r) * DD + dq);
        qv.x *= 0.125f; qv.y *= 0.125f; qv.z *= 0.125f; qv.w *= 0.125f;
        *(float4*)(sQ + r * SQP + dq) = qv;
    }

    float M[8], Z[8], Zinv[8];
    #pragma unroll
    for (int r = 0; r < 8; ++r) { M[r] = -3.4e38f; Z[r] = 0.f; }

    #pragma unroll
    for (int c = 0; c < 2; ++c) {
        __syncthreads();
        // fill sKT chunk c
        #pragma unroll
        for (int p = 0; p < 16; ++p) {
            int f4 = p * 256 + t;
            int d = f4 >> 6, cq = (f4 & 63) << 2;
            *(float4*)(sKT + d * SKP + cq) =
                *(const float4*)(g_ksumT + ((size_t)bh * DD + d) * L + c * 256 + cq);
        }
        __syncthreads();

        ull acc[8][4];
        #pragma unroll
        for (int r = 0; r < 8; ++r)
            #pragma unroll
            for (int i = 0; i < 4; ++i) acc[r][i] = 0;

        const float* bp = sKT + 4 * l;
        #pragma unroll 2
        for (int d = 0; d < DD; d += 2) {
            float2 a[8];
            #pragma unroll
            for (int r = 0; r < 8; ++r)
                a[r] = *(const float2*)(sQ + (8 * w + r) * SQP + d);
            #pragma unroll
            for (int dd = 0; dd < 2; ++dd) {
                ulonglong2 b0 = *(const ulonglong2*)(bp + (d + dd) * SKP);
                ulonglong2 b1 = *(const ulonglong2*)(bp + (d + dd) * SKP + 128);
                #pragma unroll
                for (int r = 0; r < 8; ++r) {
                    ull ar = pack2(dd ? a[r].y : a[r].x);
                    ffma2(acc[r][0], ar, b0.x);
                    ffma2(acc[r][1], ar, b0.y);
                    ffma2(acc[r][2], ar, b1.x);
                    ffma2(acc[r][3], ar, b1.y);
                }
            }
        }

        if (c == 1) __syncthreads();  // sKT reads done before sP writes below

        #pragma unroll
        for (int r = 0; r < 8; ++r) {
            int gi = qb + 8 * w + r;
            size_t orow = ((size_t)b * L + gi) * L + c * 256;
            float4 o0 = *(const float4*)(omega + orow + 4 * l);
            float4 o1 = *(const float4*)(omega + orow + 128 + 4 * l);
            int4 m0 = *(const int4*)(mask + orow + 4 * l);
            int4 m1 = *(const int4*)(mask + orow + 128 + 4 * l);
            float2 u0 = unpack2(acc[r][0]), u1 = unpack2(acc[r][1]);
            float2 u2 = unpack2(acc[r][2]), u3 = unpack2(acc[r][3]);
            float s0 = m0.x ? -1e9f : u0.x * o0.x;
            float s1 = m0.y ? -1e9f : u0.y * o0.y;
            float s2 = m0.z ? -1e9f : u1.x * o0.z;
            float s3 = m0.w ? -1e9f : u1.y * o0.w;
            float s4 = m1.x ? -1e9f : u2.x * o1.x;
            float s5 = m1.y ? -1e9f : u2.y * o1.y;
            float s6 = m1.z ? -1e9f : u3.x * o1.z;
            float s7 = m1.w ? -1e9f : u3.y * o1.w;

            float cm = fmaxf(fmaxf(fmaxf(s0, s1), fmaxf(s2, s3)),
                             fmaxf(fmaxf(s4, s5), fmaxf(s6, s7)));
            #pragma unroll
            for (int o = 16; o > 0; o >>= 1)
                cm = fmaxf(cm, __shfl_xor_sync(0xffffffffu, cm, o));
            float nM = fmaxf(M[r], cm);
            float cs = __expf(s0 - nM) + __expf(s1 - nM) + __expf(s2 - nM) + __expf(s3 - nM)
                     + __expf(s4 - nM) + __expf(s5 - nM) + __expf(s6 - nM) + __expf(s7 - nM);
            #pragma unroll
            for (int o = 16; o > 0; o >>= 1)
                cs += __shfl_xor_sync(0xffffffffu, cs, o);
            Z[r] = Z[r] * __expf(M[r] - nM) + cs;
            M[r] = nM;

            size_t arow = ((size_t)bh * L + gi) * L + c * 256;
            if (c == 0) {
                // raw store; fixed up after stats are final
                *(float4*)(attn + arow + 4 * l)       = make_float4(s0, s1, s2, s3);
                *(float4*)(attn + arow + 128 + 4 * l) = make_float4(s4, s5, s6, s7);
            } else {
                float iz = 1.0f / Z[r];
                Zinv[r] = iz;
                float p0 = __expf(s0 - M[r]) * iz, p1 = __expf(s1 - M[r]) * iz;
                float p2 = __expf(s2 - M[r]) * iz, p3 = __expf(s3 - M[r]) * iz;
                float p4 = __expf(s4 - M[r]) * iz, p5 = __expf(s5 - M[r]) * iz;
                float p6 = __expf(s6 - M[r]) * iz, p7 = __expf(s7 - M[r]) * iz;
                *(float4*)(attn + arow + 4 * l)       = make_float4(p0, p1, p2, p3);
                *(float4*)(attn + arow + 128 + 4 * l) = make_float4(p4, p5, p6, p7);
                *(float4*)(sP + (8 * w + r) * SKP + 4 * l)       = make_float4(p0, p1, p2, p3);
                *(float4*)(sP + (8 * w + r) * SKP + 128 + 4 * l) = make_float4(p4, p5, p6, p7);
            }
        }
    }

    // ------------------- PV accumulation -------------------
    const float* vbase = g_vsum + (size_t)bh * L * DD;
    ull oacc[8];
    #pragma unroll
    for (int r = 0; r < 8; ++r) oacc[r] = 0;

    auto pv_accum = [&](int jglob) {
        #pragma unroll
        for (int jc = 0; jc < 4; ++jc) {
            __syncthreads();
            #pragma unroll
            for (int p = 0; p < 4; ++p) {
                int f4 = p * 256 + t;
                int j = f4 >> 4, dq = (f4 & 15) << 2;
                *(float4*)(sV + j * SVP + dq) =
                    *(const float4*)(vbase + (size_t)(jglob + jc * 64 + j) * DD + dq);
            }
            __syncthreads();
            #pragma unroll 4
            for (int j = 0; j < 64; j += 2) {
                float2 a[8];
                #pragma unroll
                for (int r = 0; r < 8; ++r)
                    a[r] = *(const float2*)(sP + (8 * w + r) * SKP + jc * 64 + j);
                ull b0 = *(const ull*)(sV + j * SVP + 2 * l);
                ull b1 = *(const ull*)(sV + (j + 1) * SVP + 2 * l);
                #pragma unroll
                for (int r = 0; r < 8; ++r) ffma2(oacc[r], pack2(a[r].x), b0);
                #pragma unroll
                for (int r = 0; r < 8; ++r) ffma2(oacc[r], pack2(a[r].y), b1);
            }
        }
    };

    // chunk 1 first (sP already holds normalized chunk-1 P)
    pv_accum(256);

    // chunk-0 fixup: re-read own raw values (L2), normalize, write attn + sP
    __syncthreads();  // PV reads of sP done before overwrite
    #pragma unroll
    for (int r = 0; r < 8; ++r) {
        int gi = qb + 8 * w + r;
        size_t arow = ((size_t)bh * L + gi) * L;
        float4 x0 = *(const float4*)(attn + arow + 4 * l);
        float4 x1 = *(const float4*)(attn + arow + 128 + 4 * l);
        float mM = M[r], iz = Zinv[r];
        float4 p0, p1;
        p0.x = __expf(x0.x - mM) * iz; p0.y = __expf(x0.y - mM) * iz;
        p0.z = __expf(x0.z - mM) * iz; p0.w = __expf(x0.w - mM) * iz;
        p1.x = __expf(x1.x - mM) * iz; p1.y = __expf(x1.y - mM) * iz;
        p1.z = __expf(x1.z - mM) * iz; p1.w = __expf(x1.w - mM) * iz;
        *(float4*)(attn + arow + 4 * l)       = p0;
        *(float4*)(attn + arow + 128 + 4 * l) = p1;
        *(float4*)(sP + (8 * w + r) * SKP + 4 * l)       = p0;
        *(float4*)(sP + (8 * w + r) * SKP + 128 + 4 * l) = p1;
    }

    // chunk 0 PV
    pv_accum(0);

    // write O: warp rows 8w..8w+7, lane d = 2l..2l+1
    #pragma unroll
    for (int r = 0; r < 8; ++r) {
        float2 ov = unpack2(oacc[r]);
        *(float2*)(out_o + ((size_t)bh * L + qb + 8 * w + r) * DD + 2 * l) = ov;
    }
}

// ---------------------------------------------------------------------------
extern "C" void kernel_launch(void* const* d_in, const int* in_sizes, int n_in,
                              void* d_out, int out_size) {
    const float* q     = (const float*)d_in[0];
    const float* k     = (const float*)d_in[1];
    const float* v     = (const float*)d_in[2];
    const float* omega = (const float*)d_in[3];
    const int*   mask  = (const int*)d_in[4];

    float* out_o    = (float*)d_out;
    float* out_attn = out_o + (size_t)NBH * L * DD;   // [output | attn]

    const int smem2 = (64 * SQP + 64 * SKP) * (int)sizeof(float);  // 83968
    cudaFuncSetAttribute(attn_fused, cudaFuncAttributeMaxDynamicSharedMemorySize, smem2);

    reduce_kv_kernel<<<dim3(8, NBH), 256>>>(k, v);
    attn_fused<<<dim3(8, NBH), 256, smem2>>>(q, omega, mask, out_attn, out_o);
}

// round 11
// speedup vs baseline: 1.0384x; 1.0009x over previous
#include <cuda_runtime.h>
#include <cstdint>

#define NBH 64
#define L   512
#define DD  64
#define SQP 68    // sQ / sV row pad (floats)
#define SKP 260   // sKT / sP row pad (floats)
#define SVP 68

typedef unsigned long long ull;

// Scratch (device globals; no allocation in kernel_launch)
__device__ float g_ksumT[NBH * DD * L];   // [bh][d][j]  (transposed)
__device__ float g_vsum [NBH * L * DD];   // [bh][j][d]  (natural)

__device__ __forceinline__ ull pack2(float x) {
    ull r; unsigned int xi = __float_as_uint(x);
    asm("mov.b64 %0, {%1, %1};" : "=l"(r) : "r"(xi));
    return r;
}
__device__ __forceinline__ void ffma2(ull& c, ull a, ull b) {
    asm("fma.rn.f32x2 %0, %1, %2, %0;" : "+l"(c) : "l"(a), "l"(b));
}
__device__ __forceinline__ float2 unpack2(ull x) {
    float2 f;
    asm("mov.b64 {%0, %1}, %2;" : "=f"(f.x), "=f"(f.y) : "l"(x));
    return f;
}

// ---------------------------------------------------------------------------
// K1: reduce r; ksum TRANSPOSED [bh][d][j] via smem transpose, vsum natural.
// ---------------------------------------------------------------------------
__global__ __launch_bounds__(256)
void reduce_kv_kernel(const float* __restrict__ k, const float* __restrict__ v) {
    __shared__ float sT[DD * 65];
    const int t  = threadIdx.x;
    const int jb = blockIdx.x;
    const int bh = blockIdx.y;

    #pragma unroll
    for (int p = 0; p < 4; ++p) {
        int f4 = p * 256 + t;
        int jl = f4 >> 4, dq = (f4 & 15) << 2;
        size_t base = (((size_t)bh * L + jb * 64 + jl) * 4) * DD + dq;
        float4 a0 = *(const float4*)(k + base);
        float4 a1 = *(const float4*)(k + base + DD);
        float4 a2 = *(const float4*)(k + base + 2 * DD);
        float4 a3 = *(const float4*)(k + base + 3 * DD);
        sT[(dq + 0) * 65 + jl] = (a0.x + a1.x) + (a2.x + a3.x);
        sT[(dq + 1) * 65 + jl] = (a0.y + a1.y) + (a2.y + a3.y);
        sT[(dq + 2) * 65 + jl] = (a0.z + a1.z) + (a2.z + a3.z);
        sT[(dq + 3) * 65 + jl] = (a0.w + a1.w) + (a2.w + a3.w);
        float4 b0 = *(const float4*)(v + base);
        float4 b1 = *(const float4*)(v + base + DD);
        float4 b2 = *(const float4*)(v + base + 2 * DD);
        float4 b3 = *(const float4*)(v + base + 3 * DD);
        float4 vs;
        vs.x = (b0.x + b1.x) + (b2.x + b3.x);
        vs.y = (b0.y + b1.y) + (b2.y + b3.y);
        vs.z = (b0.z + b1.z) + (b2.z + b3.z);
        vs.w = (b0.w + b1.w) + (b2.w + b3.w);
        *(float4*)(g_vsum + ((size_t)bh * L + jb * 64 + jl) * DD + dq) = vs;
    }
    __syncthreads();
    #pragma unroll
    for (int p = 0; p < 4; ++p) {
        int f4 = p * 256 + t;
        int dl = f4 >> 4, jq = (f4 & 15) << 2;
        float4 o;
        o.x = sT[dl * 65 + jq + 0];
        o.y = sT[dl * 65 + jq + 1];
        o.z = sT[dl * 65 + jq + 2];
        o.w = sT[dl * 65 + jq + 3];
        *(float4*)(g_ksumT + ((size_t)bh * DD + dl) * L + jb * 64 + jq) = o;
    }
}

// ---------------------------------------------------------------------------
// K2 (fused): per CTA 64 q rows of one bh.
//   c=0: S chunk -> raw store to attn, online stats
//   c=1: S chunk -> stats finalize -> normalized P to attn + sP(smem)
//   PV chunk1 from sP; chunk0 fixup (L2 re-read, normalize, attn + sP);
//   PV chunk0; write O.
// smem: sQ[64][68] (aliased by sV) | sKT[64][260] (aliased by sP) = 84KB.
// ---------------------------------------------------------------------------
extern __shared__ float smem[];

__global__ __launch_bounds__(256, 2)
void attn_fused(const float* __restrict__ q,
                const float* __restrict__ omega,
                const int*   __restrict__ mask,
                float* __restrict__ attn,
                float* __restrict__ out_o) {
    float* sQ  = smem;              // [64][SQP]
    float* sKT = smem + 64 * SQP;   // [64][SKP]
    float* sV  = sQ;                // alias (sQ dead after QK mainloops)
    float* sP  = sKT;               // alias (sKT dead after c=1 mainloop)

    const int t  = threadIdx.x;
    const int bh = blockIdx.y;
    const int b  = bh >> 3;
    const int qb = blockIdx.x * 64;
    const int w  = t >> 5, l = t & 31;

    // fill sQ (fold 1/8)
    #pragma unroll
    for (int p = 0; p < 4; ++p) {
        int f4 = p * 256 + t;
        int r = f4 >> 4, dq = (f4 & 15) << 2;
        float4 qv = *(const float4*)(q + ((size_t)bh * L + qb + r) * DD + dq);
        qv.x *= 0.125f; qv.y *= 0.125f; qv.z *= 0.125f; qv.w *= 0.125f;
        *(float4*)(sQ + r * SQP + dq) = qv;
    }

    float M[8], Z[8], Zinv[8];
    #pragma unroll
    for (int r = 0; r < 8; ++r) { M[r] = -3.4e38f; Z[r] = 0.f; }

    #pragma unroll
    for (int c = 0; c < 2; ++c) {
        __syncthreads();
        // fill sKT chunk c
        #pragma unroll
        for (int p = 0; p < 16; ++p) {
            int f4 = p * 256 + t;
            int d = f4 >> 6, cq = (f4 & 63) << 2;
            *(float4*)(sKT + d * SKP + cq) =
                *(const float4*)(g_ksumT + ((size_t)bh * DD + d) * L + c * 256 + cq);
        }
        __syncthreads();

        ull acc[8][4];
        #pragma unroll
        for (int r = 0; r < 8; ++r)
            #pragma unroll
            for (int i = 0; i < 4; ++i) acc[r][i] = 0;

        const float* bp = sKT + 4 * l;
        #pragma unroll 2
        for (int d = 0; d < DD; d += 2) {
            float2 a[8];
            #pragma unroll
            for (int r = 0; r < 8; ++r)
                a[r] = *(const float2*)(sQ + (8 * w + r) * SQP + d);
            #pragma unroll
            for (int dd = 0; dd < 2; ++dd) {
                ulonglong2 b0 = *(const ulonglong2*)(bp + (d + dd) * SKP);
                ulonglong2 b1 = *(const ulonglong2*)(bp + (d + dd) * SKP + 128);
                #pragma unroll
                for (int r = 0; r < 8; ++r) {
                    ull ar = pack2(dd ? a[r].y : a[r].x);
                    ffma2(acc[r][0], ar, b0.x);
                    ffma2(acc[r][1], ar, b0.y);
                    ffma2(acc[r][2], ar, b1.x);
                    ffma2(acc[r][3], ar, b1.y);
                }
            }
        }

        if (c == 1) __syncthreads();  // sKT reads done before sP writes below

        #pragma unroll
        for (int r = 0; r < 8; ++r) {
            int gi = qb + 8 * w + r;
            size_t orow = ((size_t)b * L + gi) * L + c * 256;
            float4 o0 = *(const float4*)(omega + orow + 4 * l);
            float4 o1 = *(const float4*)(omega + orow + 128 + 4 * l);
            int4 m0 = *(const int4*)(mask + orow + 4 * l);
            int4 m1 = *(const int4*)(mask + orow + 128 + 4 * l);
            float2 u0 = unpack2(acc[r][0]), u1 = unpack2(acc[r][1]);
            float2 u2 = unpack2(acc[r][2]), u3 = unpack2(acc[r][3]);
            float s0 = m0.x ? -1e9f : u0.x * o0.x;
            float s1 = m0.y ? -1e9f : u0.y * o0.y;
            float s2 = m0.z ? -1e9f : u1.x * o0.z;
            float s3 = m0.w ? -1e9f : u1.y * o0.w;
            float s4 = m1.x ? -1e9f : u2.x * o1.x;
            float s5 = m1.y ? -1e9f : u2.y * o1.y;
            float s6 = m1.z ? -1e9f : u3.x * o1.z;
            float s7 = m1.w ? -1e9f : u3.y * o1.w;

            float cm = fmaxf(fmaxf(fmaxf(s0, s1), fmaxf(s2, s3)),
                             fmaxf(fmaxf(s4, s5), fmaxf(s6, s7)));
            #pragma unroll
            for (int o = 16; o > 0; o >>= 1)
                cm = fmaxf(cm, __shfl_xor_sync(0xffffffffu, cm, o));
            float nM = fmaxf(M[r], cm);
            float cs = __expf(s0 - nM) + __expf(s1 - nM) + __expf(s2 - nM) + __expf(s3 - nM)
                     + __expf(s4 - nM) + __expf(s5 - nM) + __expf(s6 - nM) + __expf(s7 - nM);
            #pragma unroll
            for (int o = 16; o > 0; o >>= 1)
                cs += __shfl_xor_sync(0xffffffffu, cs, o);
            Z[r] = Z[r] * __expf(M[r] - nM) + cs;
            M[r] = nM;

            size_t arow = ((size_t)bh * L + gi) * L + c * 256;
            if (c == 0) {
                // raw store; fixed up after stats are final
                *(float4*)(attn + arow + 4 * l)       = make_float4(s0, s1, s2, s3);
                *(float4*)(attn + arow + 128 + 4 * l) = make_float4(s4, s5, s6, s7);
            } else {
                float iz = 1.0f / Z[r];
                Zinv[r] = iz;
                float p0 = __expf(s0 - M[r]) * iz, p1 = __expf(s1 - M[r]) * iz;
                float p2 = __expf(s2 - M[r]) * iz, p3 = __expf(s3 - M[r]) * iz;
                float p4 = __expf(s4 - M[r]) * iz, p5 = __expf(s5 - M[r]) * iz;
                float p6 = __expf(s6 - M[r]) * iz, p7 = __expf(s7 - M[r]) * iz;
                *(float4*)(attn + arow + 4 * l)       = make_float4(p0, p1, p2, p3);
                *(float4*)(attn + arow + 128 + 4 * l) = make_float4(p4, p5, p6, p7);
                *(float4*)(sP + (8 * w + r) * SKP + 4 * l)       = make_float4(p0, p1, p2, p3);
                *(float4*)(sP + (8 * w + r) * SKP + 128 + 4 * l) = make_float4(p4, p5, p6, p7);
            }
        }
    }

    // ------------------- PV accumulation -------------------
    const float* vbase = g_vsum + (size_t)bh * L * DD;
    ull oacc[8];
    #pragma unroll
    for (int r = 0; r < 8; ++r) oacc[r] = 0;

    auto pv_accum = [&](int jglob) {
        #pragma unroll
        for (int jc = 0; jc < 4; ++jc) {
            __syncthreads();
            #pragma unroll
            for (int p = 0; p < 4; ++p) {
                int f4 = p * 256 + t;
                int j = f4 >> 4, dq = (f4 & 15) << 2;
                *(float4*)(sV + j * SVP + dq) =
                    *(const float4*)(vbase + (size_t)(jglob + jc * 64 + j) * DD + dq);
            }
            __syncthreads();
            #pragma unroll 4
            for (int j = 0; j < 64; j += 2) {
                float2 a[8];
                #pragma unroll
                for (int r = 0; r < 8; ++r)
                    a[r] = *(const float2*)(sP + (8 * w + r) * SKP + jc * 64 + j);
                ull b0 = *(const ull*)(sV + j * SVP + 2 * l);
                ull b1 = *(const ull*)(sV + (j + 1) * SVP + 2 * l);
                #pragma unroll
                for (int r = 0; r < 8; ++r) ffma2(oacc[r], pack2(a[r].x), b0);
                #pragma unroll
                for (int r = 0; r < 8; ++r) ffma2(oacc[r], pack2(a[r].y), b1);
            }
        }
    };

    // chunk 1 first (sP already holds normalized chunk-1 P)
    pv_accum(256);

    // chunk-0 fixup: re-read own raw values (L2), normalize, write attn + sP
    __syncthreads();  // PV reads of sP done before overwrite
    #pragma unroll
    for (int r = 0; r < 8; ++r) {
        int gi = qb + 8 * w + r;
        size_t arow = ((size_t)bh * L + gi) * L;
        float4 x0 = *(const float4*)(attn + arow + 4 * l);
        float4 x1 = *(const float4*)(attn + arow + 128 + 4 * l);
        float mM = M[r], iz = Zinv[r];
        float4 p0, p1;
        p0.x = __expf(x0.x - mM) * iz; p0.y = __expf(x0.y - mM) * iz;
        p0.z = __expf(x0.z - mM) * iz; p0.w = __expf(x0.w - mM) * iz;
        p1.x = __expf(x1.x - mM) * iz; p1.y = __expf(x1.y - mM) * iz;
        p1.z = __expf(x1.z - mM) * iz; p1.w = __expf(x1.w - mM) * iz;
        *(float4*)(attn + arow + 4 * l)       = p0;
        *(float4*)(attn + arow + 128 + 4 * l) = p1;
        *(float4*)(sP + (8 * w + r) * SKP + 4 * l)       = p0;
        *(float4*)(sP + (8 * w + r) * SKP + 128 + 4 * l) = p1;
    }

    // chunk 0 PV
    pv_accum(0);

    // write O: warp rows 8w..8w+7, lane d = 2l..2l+1
    #pragma unroll
    for (int r = 0; r < 8; ++r) {
        float2 ov = unpack2(oacc[r]);
        *(float2*)(out_o + ((size_t)bh * L + qb + 8 * w + r) * DD + 2 * l) = ov;
    }
}

// ---------------------------------------------------------------------------
extern "C" void kernel_launch(void* const* d_in, const int* in_sizes, int n_in,
                              void* d_out, int out_size) {
    const float* q     = (const float*)d_in[0];
    const float* k     = (const float*)d_in[1];
    const float* v     = (const float*)d_in[2];
    const float* omega = (const float*)d_in[3];
    const int*   mask  = (const int*)d_in[4];

    float* out_o    = (float*)d_out;
    float* out_attn = out_o + (size_t)NBH * L * DD;   // [output | attn]

    const int smem2 = (64 * SQP + 64 * SKP) * (int)sizeof(float);  // 83968
    cudaFuncSetAttribute(attn_fused, cudaFuncAttributeMaxDynamicSharedMemorySize, smem2);

    reduce_kv_kernel<<<dim3(8, NBH), 256>>>(k, v);
    attn_fused<<<dim3(8, NBH), 256, smem2>>>(q, omega, mask, out_attn, out_o);
}